// round 12
// baseline (speedup 1.0000x reference)
#include <cuda_runtime.h>
#include <cstdint>

// Problem constants (fixed by setup_inputs)
#define BB 4
#define NN 16384
#define MM 128
#define CC 128
#define SS 512
#define ROW 131            // 3 + C floats per sample
#define NBOX (BB*MM)       // 512
#define WPB  (NN/32)       // 512 mask words per box
#define BOXG 16            // boxes per mask-block (128/8 groups)
#define NROWS (NBOX*SS)    // 262144 sample rows
#define POOLED_ELEMS ((size_t)NROWS * ROW)   // 34,340,864

// Scratch (device globals — no allocation allowed)
__device__ unsigned g_mask[NBOX * WPB];  // [bm][word] inside-bitmask, 1MB
__device__ int g_idx[NBOX * SS];         // first min(cnt,512) inside indices per box
__device__ int g_cnt[NBOX];              // exact inside count

// ---------------------------------------------------------------------------
// Stage 1: mask kernel (R9 shape: unroll 4, 32 regs — best measured).
// ---------------------------------------------------------------------------
__global__ __launch_bounds__(256)
void mask_kernel(const float* __restrict__ points,
                 const float* __restrict__ boxes) {
    const int blk   = blockIdx.x;        // 0..2047
    const int grp   = blk & 7;           // box group (16 boxes)
    const int pblk  = blk >> 3;          // 0..255
    const int b     = pblk >> 6;         // batch
    const int pbase = (pblk & 63) * 256;
    const int mbase = grp * BOXG;

    __shared__ float4 sb0[BOXG];
    __shared__ float4 sb1[BOXG];

    const int tid = threadIdx.x;
    if (tid < BOXG) {
        const float* box = boxes + (b * MM + mbase + tid) * 7;
        const float cz = __fadd_rn(box[2], __fmul_rn(box[5], 0.5f));
        const float rz = box[6];
        sb0[tid] = make_float4(box[0], box[1], cz, __fmul_rn(box[5], 0.5f));
        sb1[tid] = make_float4(cosf(-rz), sinf(-rz),
                               __fmul_rn(box[3], 0.5f), __fmul_rn(box[4], 0.5f));
    }

    const int pi   = pbase + tid;
    const float* p = points + ((size_t)b * NN + pi) * 3;
    const float px = p[0];
    const float py = p[1];
    const float pz = p[2];

    __syncthreads();

    const int lane = tid & 31;
    const int word = pi >> 5;
    unsigned* mrow = g_mask + (size_t)(b * MM + mbase) * WPB + word;

    #pragma unroll 4
    for (int m = 0; m < BOXG; m++) {
        const float4 q0 = sb0[m];
        const float4 q1 = sb1[m];
        const float sx = __fsub_rn(px, q0.x);
        const float sy = __fsub_rn(py, q0.y);
        const float sz = __fsub_rn(pz, q0.z);
        // no-FMA-contraction rotate to match XLA mul-then-add ordering
        const float lx = __fsub_rn(__fmul_rn(sx, q1.x), __fmul_rn(sy, q1.y));
        const float ly = __fadd_rn(__fmul_rn(sx, q1.y), __fmul_rn(sy, q1.x));
        const bool inside = (fabsf(lx) < q1.z) && (fabsf(ly) < q1.w)
                          && (fabsf(sz) <= q0.w);
        const unsigned ball = __ballot_sync(0xffffffffu, inside);
        if (lane == 0) mrow[(size_t)m * WPB] = ball;
    }
}

// ---------------------------------------------------------------------------
// Stage 2: compaction (unchanged).
// ---------------------------------------------------------------------------
__global__ __launch_bounds__(512)
void compact_kernel(float* __restrict__ flags) {
    const int bm  = blockIdx.x;
    const int t   = threadIdx.x;
    const int lane = t & 31;
    const int wid  = t >> 5;

    const unsigned w = g_mask[(size_t)bm * WPB + t];
    const int c = __popc(w);

    int incl = c;
    #pragma unroll
    for (int d = 1; d < 32; d <<= 1) {
        int v = __shfl_up_sync(0xffffffffu, incl, d);
        if (lane >= d) incl += v;
    }

    __shared__ int wsum[16];
    __shared__ int stotal;
    if (lane == 31) wsum[wid] = incl;
    __syncthreads();
    if (t < 16) {
        int v = wsum[t];
        #pragma unroll
        for (int d = 1; d < 16; d <<= 1) {
            int u = __shfl_up_sync(0xffffu, v, d);
            if (t >= d) v += u;
        }
        wsum[t] = v;
        if (t == 15) stotal = v;
    }
    __syncthreads();

    const int warp_excl = (wid == 0) ? 0 : wsum[wid - 1];
    int rank = warp_excl + incl - c;

    unsigned ww = w;
    const int pbase = t * 32;
    while (ww && rank < SS) {
        const int bit = __ffs(ww) - 1;
        ww &= ww - 1;
        g_idx[bm * SS + rank] = pbase + bit;
        rank++;
    }

    if (t == 0) {
        const int total = stotal;
        g_cnt[bm] = total;
        if (flags) flags[bm] = (total > 0) ? 0.0f : 1.0f;
    }
}

// ---------------------------------------------------------------------------
// Stage 3: gather. One warp per TWO consecutive rows (MLP=2, best measured).
// Output stores are WRITE-THROUGH (__stwt): output lines never allocate in
// L2, keeping the 32MB feature set fully L2-resident for the gather reads.
// ---------------------------------------------------------------------------
struct RowData { float4 v; float px, py, pz; };

__device__ __forceinline__ RowData prep_row(const float* __restrict__ points,
                                            const float* __restrict__ feats,
                                            int row, int lane) {
    RowData R;
    R.v = make_float4(0.f, 0.f, 0.f, 0.f);
    R.px = 0.f; R.py = 0.f; R.pz = 0.f;

    const int s  = row & (SS - 1);
    const int bm = row >> 9;
    const int b  = bm >> 7;
    const int cnt = g_cnt[bm];
    if (cnt != 0) {
        const int r   = (s < cnt) ? s : (s % cnt);
        const int idx = g_idx[bm * SS + r];
        const float4* f = (const float4*)(feats + ((size_t)b * NN + idx) * CC);
        R.v = __ldg(f + lane);
        if (lane == 0) {
            const float* p = points + ((size_t)b * NN + idx) * 3;
            R.px = __ldg(p + 0); R.py = __ldg(p + 1); R.pz = __ldg(p + 2);
        }
    }
    return R;
}

__device__ __forceinline__ void emit_row(float* __restrict__ out,
                                         int row, int lane,
                                         const RowData& R) {
    const int a0 = row & 3;             // first 16B-aligned float offset in row
    float* o = out + (size_t)row * ROW;
    const float4 v = R.v;

    float pvy = __shfl_up_sync(0xffffffffu, v.y, 1);
    float pvz = __shfl_up_sync(0xffffffffu, v.z, 1);
    float pvw = __shfl_up_sync(0xffffffffu, v.w, 1);
    if (lane == 0) { pvy = R.px; pvz = R.py; pvw = R.pz; }

    float4 q;
    if      (a0 == 0) q = make_float4(pvy, pvz, pvw, v.x);
    else if (a0 == 1) q = make_float4(pvz, pvw, v.x, v.y);
    else if (a0 == 2) q = make_float4(pvw, v.x, v.y, v.z);
    else              q = v;

    __stwt((float4*)(o + a0) + lane, q);

    if (lane == 0) {                    // head floats [0, a0): points
        if (a0 > 0) __stwt(o + 0, R.px);
        if (a0 > 1) __stwt(o + 1, R.py);
        if (a0 > 2) __stwt(o + 2, R.pz);
    }
    if (lane == 31) {                   // tail floats [a0+128, 131)
        if (a0 == 0) { __stwt(o + 128, v.y); __stwt(o + 129, v.z); __stwt(o + 130, v.w); }
        else if (a0 == 1) { __stwt(o + 129, v.z); __stwt(o + 130, v.w); }
        else if (a0 == 2) { __stwt(o + 130, v.w); }
    }
}

__global__ __launch_bounds__(256)
void phase2_kernel(const float* __restrict__ points,
                   const float* __restrict__ feats,
                   float* __restrict__ out) {
    const int gwarp = (int)((blockIdx.x * blockDim.x + threadIdx.x) >> 5);
    const int lane  = threadIdx.x & 31;
    const int row0  = gwarp * 2;

    RowData r0 = prep_row(points, feats, row0 + 0, lane);
    RowData r1 = prep_row(points, feats, row0 + 1, lane);
    emit_row(out, row0 + 0, lane, r0);
    emit_row(out, row0 + 1, lane, r1);
}

extern "C" void kernel_launch(void* const* d_in, const int* in_sizes, int n_in,
                              void* d_out, int out_size) {
    const float* points = (const float*)d_in[0];   // (B, N, 3)
    const float* feats  = (const float*)d_in[1];   // (B, N, C)
    const float* boxes  = (const float*)d_in[2];   // (B, M, 7)
    float* out = (float*)d_out;

    float* flags = ((size_t)out_size >= POOLED_ELEMS + NBOX)
                 ? (out + POOLED_ELEMS) : nullptr;

    mask_kernel<<<2048, 256>>>(points, boxes);
    compact_kernel<<<NBOX, 512>>>(flags);

    // NROWS/2 warps, 8 warps per block -> 16384 blocks
    phase2_kernel<<<NROWS / 2 / 8, 256>>>(points, feats, out);
}

// round 13
// speedup vs baseline: 1.1394x; 1.1394x over previous
#include <cuda_runtime.h>
#include <cstdint>

// Problem constants (fixed by setup_inputs)
#define BB 4
#define NN 16384
#define MM 128
#define CC 128
#define SS 512
#define ROW 131            // 3 + C floats per sample
#define NBOX (BB*MM)       // 512
#define WPB  (NN/32)       // 512 mask words per box
#define BOXG 16            // boxes per mask-block (128/8 groups)
#define NROWS (NBOX*SS)    // 262144 sample rows
#define POOLED_ELEMS ((size_t)NROWS * ROW)   // 34,340,864

// Scratch (device globals — no allocation allowed)
__device__ unsigned g_mask[NBOX * WPB];  // [bm][word] inside-bitmask, 1MB
__device__ int g_idx[NBOX * SS];         // first min(cnt,512) inside indices per box
__device__ int g_cnt[NBOX];              // exact inside count

// ---------------------------------------------------------------------------
// Stage 1: mask kernel. Two points per thread: box params loaded once per
// iteration serve two tests (amortizes LDS + loop overhead).
// Grid: 1024 blocks x 256 threads (8 box-groups x 32 point-blocks x 4 batches),
// each block covers 512 points.
// ---------------------------------------------------------------------------
__global__ __launch_bounds__(256)
void mask_kernel(const float* __restrict__ points,
                 const float* __restrict__ boxes) {
    const int blk   = blockIdx.x;        // 0..1023
    const int grp   = blk & 7;           // box group (16 boxes)
    const int pblk  = blk >> 3;          // 0..127
    const int b     = pblk >> 5;         // batch  (32 point-blocks per batch)
    const int pbase = (pblk & 31) * 512; // first point in batch for this block
    const int mbase = grp * BOXG;

    __shared__ float4 sb0[BOXG];
    __shared__ float4 sb1[BOXG];

    const int tid = threadIdx.x;
    if (tid < BOXG) {
        const float* box = boxes + (b * MM + mbase + tid) * 7;
        const float cz = __fadd_rn(box[2], __fmul_rn(box[5], 0.5f));
        const float rz = box[6];
        sb0[tid] = make_float4(box[0], box[1], cz, __fmul_rn(box[5], 0.5f));
        sb1[tid] = make_float4(cosf(-rz), sinf(-rz),
                               __fmul_rn(box[3], 0.5f), __fmul_rn(box[4], 0.5f));
    }

    const int pi0 = pbase + tid;                  // point A
    const int pi1 = pi0 + 256;                    // point B
    const float* pA = points + ((size_t)b * NN + pi0) * 3;
    const float* pB = points + ((size_t)b * NN + pi1) * 3;
    const float px0 = pA[0], py0 = pA[1], pz0 = pA[2];
    const float px1 = pB[0], py1 = pB[1], pz1 = pB[2];

    __syncthreads();

    const int lane  = tid & 31;
    const int word0 = pi0 >> 5;                   // mask word for point A
    unsigned* mrow = g_mask + (size_t)(b * MM + mbase) * WPB + word0;
    // point B's word = word0 + 8 (256 points later)

    #pragma unroll 4
    for (int m = 0; m < BOXG; m++) {
        const float4 q0 = sb0[m];
        const float4 q1 = sb1[m];

        // no-FMA-contraction rotate to match XLA mul-then-add ordering
        const float sx0 = __fsub_rn(px0, q0.x);
        const float sy0 = __fsub_rn(py0, q0.y);
        const float sz0 = __fsub_rn(pz0, q0.z);
        const float lx0 = __fsub_rn(__fmul_rn(sx0, q1.x), __fmul_rn(sy0, q1.y));
        const float ly0 = __fadd_rn(__fmul_rn(sx0, q1.y), __fmul_rn(sy0, q1.x));
        const bool in0 = (fabsf(lx0) < q1.z) && (fabsf(ly0) < q1.w)
                       && (fabsf(sz0) <= q0.w);

        const float sx1 = __fsub_rn(px1, q0.x);
        const float sy1 = __fsub_rn(py1, q0.y);
        const float sz1 = __fsub_rn(pz1, q0.z);
        const float lx1 = __fsub_rn(__fmul_rn(sx1, q1.x), __fmul_rn(sy1, q1.y));
        const float ly1 = __fadd_rn(__fmul_rn(sx1, q1.y), __fmul_rn(sy1, q1.x));
        const bool in1 = (fabsf(lx1) < q1.z) && (fabsf(ly1) < q1.w)
                       && (fabsf(sz1) <= q0.w);

        const unsigned b0 = __ballot_sync(0xffffffffu, in0);
        const unsigned b1 = __ballot_sync(0xffffffffu, in1);
        if (lane == 0) {
            mrow[(size_t)m * WPB + 0] = b0;
            mrow[(size_t)m * WPB + 8] = b1;
        }
    }
}

// ---------------------------------------------------------------------------
// Stage 2: compaction (unchanged).
// ---------------------------------------------------------------------------
__global__ __launch_bounds__(512)
void compact_kernel(float* __restrict__ flags) {
    const int bm  = blockIdx.x;
    const int t   = threadIdx.x;
    const int lane = t & 31;
    const int wid  = t >> 5;

    const unsigned w = g_mask[(size_t)bm * WPB + t];
    const int c = __popc(w);

    int incl = c;
    #pragma unroll
    for (int d = 1; d < 32; d <<= 1) {
        int v = __shfl_up_sync(0xffffffffu, incl, d);
        if (lane >= d) incl += v;
    }

    __shared__ int wsum[16];
    __shared__ int stotal;
    if (lane == 31) wsum[wid] = incl;
    __syncthreads();
    if (t < 16) {
        int v = wsum[t];
        #pragma unroll
        for (int d = 1; d < 16; d <<= 1) {
            int u = __shfl_up_sync(0xffffu, v, d);
            if (t >= d) v += u;
        }
        wsum[t] = v;
        if (t == 15) stotal = v;
    }
    __syncthreads();

    const int warp_excl = (wid == 0) ? 0 : wsum[wid - 1];
    int rank = warp_excl + incl - c;

    unsigned ww = w;
    const int pbase = t * 32;
    while (ww && rank < SS) {
        const int bit = __ffs(ww) - 1;
        ww &= ww - 1;
        g_idx[bm * SS + rank] = pbase + bit;
        rank++;
    }

    if (t == 0) {
        const int total = stotal;
        g_cnt[bm] = total;
        if (flags) flags[bm] = (total > 0) ? 0.0f : 1.0f;
    }
}

// ---------------------------------------------------------------------------
// Stage 3: gather (exact R9 shape, the 43.5us best: MLP=2, __stcs stores,
// register realignment -> one aligned STG.128 per lane + head/tail scalars).
// ---------------------------------------------------------------------------
struct RowData { float4 v; float px, py, pz; };

__device__ __forceinline__ RowData prep_row(const float* __restrict__ points,
                                            const float* __restrict__ feats,
                                            int row, int lane) {
    RowData R;
    R.v = make_float4(0.f, 0.f, 0.f, 0.f);
    R.px = 0.f; R.py = 0.f; R.pz = 0.f;

    const int s  = row & (SS - 1);
    const int bm = row >> 9;
    const int b  = bm >> 7;
    const int cnt = g_cnt[bm];
    if (cnt != 0) {
        const int r   = (s < cnt) ? s : (s % cnt);
        const int idx = g_idx[bm * SS + r];
        const float4* f = (const float4*)(feats + ((size_t)b * NN + idx) * CC);
        R.v = __ldg(f + lane);
        if (lane == 0) {
            const float* p = points + ((size_t)b * NN + idx) * 3;
            R.px = __ldg(p + 0); R.py = __ldg(p + 1); R.pz = __ldg(p + 2);
        }
    }
    return R;
}

__device__ __forceinline__ void emit_row(float* __restrict__ out,
                                         int row, int lane,
                                         const RowData& R) {
    const int a0 = row & 3;             // first 16B-aligned float offset in row
    float* o = out + (size_t)row * ROW;
    const float4 v = R.v;

    float pvy = __shfl_up_sync(0xffffffffu, v.y, 1);
    float pvz = __shfl_up_sync(0xffffffffu, v.z, 1);
    float pvw = __shfl_up_sync(0xffffffffu, v.w, 1);
    if (lane == 0) { pvy = R.px; pvz = R.py; pvw = R.pz; }

    float4 q;
    if      (a0 == 0) q = make_float4(pvy, pvz, pvw, v.x);
    else if (a0 == 1) q = make_float4(pvz, pvw, v.x, v.y);
    else if (a0 == 2) q = make_float4(pvw, v.x, v.y, v.z);
    else              q = v;

    __stcs((float4*)(o + a0) + lane, q);

    if (lane == 0) {                    // head floats [0, a0): points
        if (a0 > 0) __stcs(o + 0, R.px);
        if (a0 > 1) __stcs(o + 1, R.py);
        if (a0 > 2) __stcs(o + 2, R.pz);
    }
    if (lane == 31) {                   // tail floats [a0+128, 131)
        if (a0 == 0) { __stcs(o + 128, v.y); __stcs(o + 129, v.z); __stcs(o + 130, v.w); }
        else if (a0 == 1) { __stcs(o + 129, v.z); __stcs(o + 130, v.w); }
        else if (a0 == 2) { __stcs(o + 130, v.w); }
    }
}

__global__ __launch_bounds__(256)
void phase2_kernel(const float* __restrict__ points,
                   const float* __restrict__ feats,
                   float* __restrict__ out) {
    const int gwarp = (int)((blockIdx.x * blockDim.x + threadIdx.x) >> 5);
    const int lane  = threadIdx.x & 31;
    const int row0  = gwarp * 2;

    RowData r0 = prep_row(points, feats, row0 + 0, lane);
    RowData r1 = prep_row(points, feats, row0 + 1, lane);
    emit_row(out, row0 + 0, lane, r0);
    emit_row(out, row0 + 1, lane, r1);
}

extern "C" void kernel_launch(void* const* d_in, const int* in_sizes, int n_in,
                              void* d_out, int out_size) {
    const float* points = (const float*)d_in[0];   // (B, N, 3)
    const float* feats  = (const float*)d_in[1];   // (B, N, C)
    const float* boxes  = (const float*)d_in[2];   // (B, M, 7)
    float* out = (float*)d_out;

    float* flags = ((size_t)out_size >= POOLED_ELEMS + NBOX)
                 ? (out + POOLED_ELEMS) : nullptr;

    mask_kernel<<<1024, 256>>>(points, boxes);
    compact_kernel<<<NBOX, 512>>>(flags);

    // NROWS/2 warps, 8 warps per block -> 16384 blocks
    phase2_kernel<<<NROWS / 2 / 8, 256>>>(points, feats, out);
}